// round 3
// baseline (speedup 1.0000x reference)
#include <cuda_runtime.h>
#include <math.h>

#define DIM   1024
#define NUM_F 16
#define NB    4
#define SEQ   2048
#define MTOK  (NB * SEQ)   // 8192

// ---------------- scratch (static device globals; allocation-free rule) ------
__device__ float g_v[MTOK * DIM];           // 32 MB  v = x@Wv^T + bv
__device__ float g_p[NB * SEQ * SEQ];       // 64 MB  softmax(QK^T) rows
__device__ float g_kanq[MTOK * NUM_F];
__device__ float g_kank[MTOK * NUM_F];
__device__ float g_Cq[NUM_F * DIM];         // basis @ Wq  (folded projection)
__device__ float g_Ck[NUM_F * DIM];
__device__ float g_cq[NUM_F];               // basis @ bq
__device__ float g_ck[NUM_F];

// ---------------- K1: fold basis into Wq/Wk --------------------------------
// Cq[f,d] = sum_e basis[f,e] * Wq[e,d];  cq[f] = sum_e basis[f,e]*bq[e]
__global__ void fold_kernel(const float* __restrict__ basis,
                            const float* __restrict__ Wq, const float* __restrict__ bq,
                            const float* __restrict__ Wk, const float* __restrict__ bk)
{
    int d = blockIdx.x * blockDim.x + threadIdx.x;  // 0..1023
    int f = blockIdx.y;                             // 0..15
    float aq = 0.f, ak = 0.f;
    for (int e = 0; e < DIM; e++) {
        float be = basis[f * DIM + e];
        aq = fmaf(be, Wq[e * DIM + d], aq);
        ak = fmaf(be, Wk[e * DIM + d], ak);
    }
    g_Cq[f * DIM + d] = aq;
    g_Ck[f * DIM + d] = ak;
    if (blockIdx.x == 0 && threadIdx.x == 0) {
        float sq = 0.f, sk = 0.f;
        for (int e = 0; e < DIM; e++) {
            sq = fmaf(basis[f * DIM + e], bq[e], sq);
            sk = fmaf(basis[f * DIM + e], bk[e], sk);
        }
        g_cq[f] = sq;
        g_ck[f] = sk;
    }
}

// ---------------- K2: kan_q / kan_k = x @ C^T + c ---------------------------
// One warp per token row; 8 rows per 256-thread block.
__global__ void kan_kernel(const float* __restrict__ x)
{
    int warp = threadIdx.x >> 5;
    int lane = threadIdx.x & 31;
    int m = blockIdx.x * 8 + warp;
    float aq[NUM_F], ak[NUM_F];
#pragma unroll
    for (int f = 0; f < NUM_F; f++) { aq[f] = 0.f; ak[f] = 0.f; }
    const float* xr = x + (size_t)m * DIM;
    for (int d = lane; d < DIM; d += 32) {
        float xv = xr[d];
#pragma unroll
        for (int f = 0; f < NUM_F; f++) {
            aq[f] = fmaf(xv, g_Cq[f * DIM + d], aq[f]);
            ak[f] = fmaf(xv, g_Ck[f * DIM + d], ak[f]);
        }
    }
#pragma unroll
    for (int f = 0; f < NUM_F; f++) {
#pragma unroll
        for (int off = 16; off; off >>= 1) {
            aq[f] += __shfl_down_sync(0xffffffffu, aq[f], off);
            ak[f] += __shfl_down_sync(0xffffffffu, ak[f], off);
        }
    }
    if (lane == 0) {
#pragma unroll
        for (int f = 0; f < NUM_F; f++) {
            g_kanq[m * NUM_F + f] = aq[f] + g_cq[f];
            g_kank[m * NUM_F + f] = ak[f] + g_ck[f];
        }
    }
}

// ---------------- K4: scores (rank-16) + softmax -> P -----------------------
__global__ void attn_softmax_kernel()
{
    __shared__ float srow[SEQ];   // 8 KB row buffer
    __shared__ float red[8];
    int r = blockIdx.x;           // 0..8191 (global query row)
    int b = r >> 11;
    int tid = threadIdx.x;

    float qf[NUM_F];
#pragma unroll
    for (int f = 0; f < NUM_F; f++) qf[f] = g_kanq[r * NUM_F + f];
    const float* kb = g_kank + (size_t)b * SEQ * NUM_F;
    const float scale = 1.0f / 32.0f;   // 1/sqrt(1024)

    float lmax = -INFINITY;
    for (int j = tid; j < SEQ; j += 256) {
        const float* kr = kb + j * NUM_F;
        float s = 0.f;
#pragma unroll
        for (int f = 0; f < NUM_F; f++) s = fmaf(qf[f], kr[f], s);
        s *= scale;
        srow[j] = s;
        lmax = fmaxf(lmax, s);
    }
#pragma unroll
    for (int off = 16; off; off >>= 1)
        lmax = fmaxf(lmax, __shfl_xor_sync(0xffffffffu, lmax, off));
    if ((tid & 31) == 0) red[tid >> 5] = lmax;
    __syncthreads();
    float bmax = red[0];
#pragma unroll
    for (int w = 1; w < 8; w++) bmax = fmaxf(bmax, red[w]);

    float lsum = 0.f;
    for (int j = tid; j < SEQ; j += 256) {
        float e = __expf(srow[j] - bmax);
        srow[j] = e;
        lsum += e;
    }
#pragma unroll
    for (int off = 16; off; off >>= 1)
        lsum += __shfl_xor_sync(0xffffffffu, lsum, off);
    __syncthreads();                    // protect red before rewrite
    if ((tid & 31) == 0) red[tid >> 5] = lsum;
    __syncthreads();
    float bsum = 0.f;
#pragma unroll
    for (int w = 0; w < 8; w++) bsum += red[w];
    float inv = 1.0f / bsum;

    float* pr = g_p + (size_t)r * SEQ;
    for (int j = tid; j < SEQ; j += 256) pr[j] = srow[j] * inv;
}

// ---------------- K3 / K5: tiled fp32 SGEMM ---------------------------------
// BT=true : C = A[M,K] @ B[N,K]^T (+bias)   (v = x @ Wv^T + bv)
// BT=false: C = A[M,K] @ B[K,N]             (out = P @ v, batched via blockIdx.z)
#define BM 128
#define BN 128
#define BKT 16
#define TM 8
#define TN 8

template <bool BT>
__global__ __launch_bounds__(256) void sgemm_kernel(
    const float* __restrict__ Ag, const float* __restrict__ Bg,
    const float* __restrict__ bias, float* __restrict__ Cg,
    int Kdim, int Ndim,
    long strideA, long strideB, long strideC)
{
    __shared__ float As[BKT][BM];
    __shared__ float Bs[BKT][BN];
    const float* A = Ag + (size_t)blockIdx.z * strideA;
    const float* Bp = Bg + (size_t)blockIdx.z * strideB;
    float* C = Cg + (size_t)blockIdx.z * strideC;
    int m0 = blockIdx.y * BM;
    int n0 = blockIdx.x * BN;
    int tid = threadIdx.x;

    int a_row = tid >> 2;            // 0..63
    int a_k4 = (tid & 3) * 4;        // k offset
    int tx = tid & 15, ty = tid >> 4;

    float acc[TM][TN];
#pragma unroll
    for (int i = 0; i < TM; i++)
#pragma unroll
        for (int j = 0; j < TN; j++) acc[i][j] = 0.f;

    for (int k0 = 0; k0 < Kdim; k0 += BKT) {
        // A tile: As[k][m] = A[m0+m][k0+k]
#pragma unroll
        for (int i = 0; i < 2; i++) {
            int r = a_row + i * 64;
            float4 v = *(const float4*)(A + (size_t)(m0 + r) * Kdim + k0 + a_k4);
            As[a_k4 + 0][r] = v.x; As[a_k4 + 1][r] = v.y;
            As[a_k4 + 2][r] = v.z; As[a_k4 + 3][r] = v.w;
        }
        if (BT) {
            // B tile (N,K): Bs[k][n] = B[n0+n][k0+k]
#pragma unroll
            for (int i = 0; i < 2; i++) {
                int r = a_row + i * 64;
                float4 v = *(const float4*)(Bp + (size_t)(n0 + r) * Kdim + k0 + a_k4);
                Bs[a_k4 + 0][r] = v.x; Bs[a_k4 + 1][r] = v.y;
                Bs[a_k4 + 2][r] = v.z; Bs[a_k4 + 3][r] = v.w;
            }
        } else {
            // B tile (K,N): Bs[k][n] = B[k0+k][n0+n]
            int b_k = tid >> 5;           // 0..7
            int b_n = (tid & 31) * 4;     // 0..124
#pragma unroll
            for (int i = 0; i < 2; i++) {
                int kr = b_k + i * 8;
                float4 v = *(const float4*)(Bp + (size_t)(k0 + kr) * Ndim + n0 + b_n);
                *(float4*)&Bs[kr][b_n] = v;
            }
        }
        __syncthreads();
#pragma unroll
        for (int kk = 0; kk < BKT; kk++) {
            float a[TM], bfr[TN];
            *(float4*)&a[0]   = *(const float4*)&As[kk][ty * TM];
            *(float4*)&a[4]   = *(const float4*)&As[kk][ty * TM + 4];
            *(float4*)&bfr[0] = *(const float4*)&Bs[kk][tx * TN];
            *(float4*)&bfr[4] = *(const float4*)&Bs[kk][tx * TN + 4];
#pragma unroll
            for (int i = 0; i < TM; i++)
#pragma unroll
                for (int j = 0; j < TN; j++)
                    acc[i][j] = fmaf(a[i], bfr[j], acc[i][j]);
        }
        __syncthreads();
    }
#pragma unroll
    for (int i = 0; i < TM; i++) {
        int m = m0 + ty * TM + i;
#pragma unroll
        for (int j = 0; j < TN; j += 4) {
            int n = n0 + tx * TN + j;
            float4 v = make_float4(acc[i][j], acc[i][j + 1], acc[i][j + 2], acc[i][j + 3]);
            if (bias) {
                v.x += bias[n]; v.y += bias[n + 1];
                v.z += bias[n + 2]; v.w += bias[n + 3];
            }
            *(float4*)(C + (size_t)m * Ndim + n) = v;
        }
    }
}

// ---------------- launch -----------------------------------------------------
extern "C" void kernel_launch(void* const* d_in, const int* in_sizes, int n_in,
                              void* d_out, int out_size)
{
    const float* x     = (const float*)d_in[0];
    const float* basis = (const float*)d_in[1];
    const float* Wq    = (const float*)d_in[2];
    const float* bq    = (const float*)d_in[3];
    const float* Wk    = (const float*)d_in[4];
    const float* bk    = (const float*)d_in[5];
    const float* Wv    = (const float*)d_in[6];
    const float* bv    = (const float*)d_in[7];
    float* out = (float*)d_out;

    float *pv, *pp;
    cudaGetSymbolAddress((void**)&pv, g_v);
    cudaGetSymbolAddress((void**)&pp, g_p);

    // K1: fold basis into Q/K projections (16x1024 each)
    fold_kernel<<<dim3(4, 16), 256>>>(basis, Wq, bq, Wk, bk);

    // K2: kan_q, kan_k  [8192,16]
    kan_kernel<<<MTOK / 8, 256>>>(x);

    // K3: v = x @ Wv^T + bv   [8192,1024]
    sgemm_kernel<true><<<dim3(DIM / BN, MTOK / BM, 1), 256>>>(
        x, Wv, bv, pv, DIM, DIM, 0L, 0L, 0L);

    // K4: P = softmax(kan_q @ kan_k^T / 32)   [4,2048,2048]
    attn_softmax_kernel<<<MTOK, 256>>>();

    // K5: out = P @ v   batched [4] x [2048,2048]@[2048,1024]
    sgemm_kernel<false><<<dim3(DIM / BN, SEQ / BM, NB), 256>>>(
        pp, pv, nullptr, out,
        SEQ, DIM,
        (long)SEQ * SEQ, (long)SEQ * DIM, (long)SEQ * DIM);
}

// round 4
// speedup vs baseline: 1.3718x; 1.3718x over previous
#include <cuda_runtime.h>
#include <math.h>

#define DIM   1024
#define NUM_F 16
#define NB    4
#define SEQ   2048
#define MTOK  (NB * SEQ)   // 8192

// ---------------- scratch (static device globals; allocation-free rule) ------
__device__ float g_v[MTOK * DIM];           // 32 MB  v = x@Wv^T + bv
__device__ float g_p[NB * SEQ * SEQ];       // 64 MB  scores -> softmax in place
__device__ float g_kanq[MTOK * NUM_F];
__device__ float g_kank[MTOK * NUM_F];
__device__ float g_Cq[NUM_F * DIM];         // basis @ Wq  (folded projection)
__device__ float g_Ck[NUM_F * DIM];
__device__ float g_cq[NUM_F];               // basis @ bq
__device__ float g_ck[NUM_F];

// ---------------- K1: fold basis into Wq/Wk --------------------------------
__global__ void fold_kernel(const float* __restrict__ basis,
                            const float* __restrict__ Wq, const float* __restrict__ bq,
                            const float* __restrict__ Wk, const float* __restrict__ bk)
{
    int d = blockIdx.x * blockDim.x + threadIdx.x;  // 0..1023
    int f = blockIdx.y;                             // 0..15
    float aq = 0.f, ak = 0.f;
    for (int e = 0; e < DIM; e++) {
        float be = basis[f * DIM + e];
        aq = fmaf(be, Wq[e * DIM + d], aq);
        ak = fmaf(be, Wk[e * DIM + d], ak);
    }
    g_Cq[f * DIM + d] = aq;
    g_Ck[f * DIM + d] = ak;
    if (blockIdx.x == 0 && threadIdx.x == 0) {
        float sq = 0.f, sk = 0.f;
        for (int e = 0; e < DIM; e++) {
            sq = fmaf(basis[f * DIM + e], bq[e], sq);
            sk = fmaf(basis[f * DIM + e], bk[e], sk);
        }
        g_cq[f] = sq;
        g_ck[f] = sk;
    }
}

// ---------------- K2: kan_q / kan_k = x @ C^T + c ---------------------------
__global__ void kan_kernel(const float* __restrict__ x)
{
    int warp = threadIdx.x >> 5;
    int lane = threadIdx.x & 31;
    int m = blockIdx.x * 8 + warp;
    float aq[NUM_F], ak[NUM_F];
#pragma unroll
    for (int f = 0; f < NUM_F; f++) { aq[f] = 0.f; ak[f] = 0.f; }
    const float* xr = x + (size_t)m * DIM;
    for (int d = lane; d < DIM; d += 32) {
        float xv = xr[d];
#pragma unroll
        for (int f = 0; f < NUM_F; f++) {
            aq[f] = fmaf(xv, g_Cq[f * DIM + d], aq[f]);
            ak[f] = fmaf(xv, g_Ck[f * DIM + d], ak[f]);
        }
    }
#pragma unroll
    for (int f = 0; f < NUM_F; f++) {
#pragma unroll
        for (int off = 16; off; off >>= 1) {
            aq[f] += __shfl_down_sync(0xffffffffu, aq[f], off);
            ak[f] += __shfl_down_sync(0xffffffffu, ak[f], off);
        }
    }
    if (lane == 0) {
#pragma unroll
        for (int f = 0; f < NUM_F; f++) {
            g_kanq[m * NUM_F + f] = aq[f] + g_cq[f];
            g_kank[m * NUM_F + f] = ak[f] + g_ck[f];
        }
    }
}

// ---------------- K4a: rank-16 score GEMM  S = kanq @ kank^T * scale --------
// Block: 128x128 output tile, 256 threads, K=16 fully staged in smem.
__global__ __launch_bounds__(256) void score_kernel()
{
    __shared__ float Qs[NUM_F][128];   // [k][m]
    __shared__ float Ks[NUM_F][128];   // [k][n]
    int b  = blockIdx.z;
    int m0 = blockIdx.y * 128;
    int n0 = blockIdx.x * 128;
    int tid = threadIdx.x;

    // Tiles are contiguous 2048-float blocks (row stride == NUM_F).
    const float* qg = g_kanq + ((size_t)b * SEQ + m0) * NUM_F;
    const float* kg = g_kank + ((size_t)b * SEQ + n0) * NUM_F;
#pragma unroll
    for (int it = 0; it < 2; it++) {
        int f4 = tid + it * 256;             // float4 index 0..511
        int m  = f4 >> 2;
        int k4 = (f4 & 3) * 4;
        float4 vq = ((const float4*)qg)[f4];
        float4 vk = ((const float4*)kg)[f4];
        Qs[k4 + 0][m] = vq.x; Qs[k4 + 1][m] = vq.y;
        Qs[k4 + 2][m] = vq.z; Qs[k4 + 3][m] = vq.w;
        Ks[k4 + 0][m] = vk.x; Ks[k4 + 1][m] = vk.y;
        Ks[k4 + 2][m] = vk.z; Ks[k4 + 3][m] = vk.w;
    }
    __syncthreads();

    int tx = tid & 15, ty = tid >> 4;
    float acc[8][8];
#pragma unroll
    for (int i = 0; i < 8; i++)
#pragma unroll
        for (int j = 0; j < 8; j++) acc[i][j] = 0.f;

#pragma unroll
    for (int kk = 0; kk < NUM_F; kk++) {
        float a[8], bb[8];
        *(float4*)&a[0]  = *(const float4*)&Qs[kk][ty * 4];
        *(float4*)&a[4]  = *(const float4*)&Qs[kk][ty * 4 + 64];
        *(float4*)&bb[0] = *(const float4*)&Ks[kk][tx * 4];
        *(float4*)&bb[4] = *(const float4*)&Ks[kk][tx * 4 + 64];
#pragma unroll
        for (int i = 0; i < 8; i++)
#pragma unroll
            for (int j = 0; j < 8; j++)
                acc[i][j] = fmaf(a[i], bb[j], acc[i][j]);
    }

    const float scale = 1.0f / 32.0f;   // 1/sqrt(1024)
    float* pg = g_p + (size_t)b * SEQ * SEQ;
#pragma unroll
    for (int i = 0; i < 8; i++) {
        int m = m0 + ty * 4 + (i & 3) + (i >> 2) * 64;
        float* prow = pg + (size_t)m * SEQ + n0;
#pragma unroll
        for (int jh = 0; jh < 2; jh++) {
            int n = tx * 4 + jh * 64;
            float4 v = make_float4(acc[i][jh * 4 + 0] * scale, acc[i][jh * 4 + 1] * scale,
                                   acc[i][jh * 4 + 2] * scale, acc[i][jh * 4 + 3] * scale);
            *(float4*)(prow + n) = v;
        }
    }
}

// ---------------- K4b: in-place row softmax ---------------------------------
__global__ __launch_bounds__(256) void softmax_kernel()
{
    __shared__ float4 srow[SEQ / 4];   // 8 KB
    __shared__ float red[8];
    int r = blockIdx.x;
    int tid = threadIdx.x;
    int lane = tid & 31, wid = tid >> 5;
    float4* pr = (float4*)(g_p + (size_t)r * SEQ);

    float lmax = -INFINITY;
#pragma unroll
    for (int it = 0; it < 2; it++) {
        int j = tid + it * 256;
        float4 v = pr[j];
        srow[j] = v;
        lmax = fmaxf(lmax, fmaxf(fmaxf(v.x, v.y), fmaxf(v.z, v.w)));
    }
#pragma unroll
    for (int off = 16; off; off >>= 1)
        lmax = fmaxf(lmax, __shfl_xor_sync(0xffffffffu, lmax, off));
    if (lane == 0) red[wid] = lmax;
    __syncthreads();
    float bmax = red[0];
#pragma unroll
    for (int w = 1; w < 8; w++) bmax = fmaxf(bmax, red[w]);

    float lsum = 0.f;
#pragma unroll
    for (int it = 0; it < 2; it++) {
        int j = tid + it * 256;
        float4 v = srow[j];
        v.x = __expf(v.x - bmax); v.y = __expf(v.y - bmax);
        v.z = __expf(v.z - bmax); v.w = __expf(v.w - bmax);
        srow[j] = v;
        lsum += v.x + v.y + v.z + v.w;
    }
#pragma unroll
    for (int off = 16; off; off >>= 1)
        lsum += __shfl_xor_sync(0xffffffffu, lsum, off);
    __syncthreads();                   // all reads of red done before rewrite
    if (lane == 0) red[wid] = lsum;
    __syncthreads();
    float bsum = 0.f;
#pragma unroll
    for (int w = 0; w < 8; w++) bsum += red[w];
    float inv = 1.0f / bsum;

#pragma unroll
    for (int it = 0; it < 2; it++) {
        int j = tid + it * 256;
        float4 v = srow[j];
        v.x *= inv; v.y *= inv; v.z *= inv; v.w *= inv;
        pr[j] = v;
    }
}

// ---------------- K3 / K5: double-buffered tiled fp32 SGEMM -----------------
// BT=true : C = A[M,K] @ B[N,K]^T (+bias)   (v = x @ Wv^T + bv)
// BT=false: C = A[M,K] @ B[K,N]             (out = P @ v, batched via blockIdx.z)
#define BM 128
#define BN 128
#define BKT 16

template <bool BT>
__global__ __launch_bounds__(256) void sgemm_kernel(
    const float* __restrict__ Ag, const float* __restrict__ Bg,
    const float* __restrict__ bias, float* __restrict__ Cg,
    int Kdim, int Ndim,
    long strideA, long strideB, long strideC)
{
    __shared__ float As[2][BKT][BM];
    __shared__ float Bs[2][BKT][BN];
    const float* A  = Ag + (size_t)blockIdx.z * strideA;
    const float* Bp = Bg + (size_t)blockIdx.z * strideB;
    float* C        = Cg + (size_t)blockIdx.z * strideC;
    int m0 = blockIdx.y * BM;
    int n0 = blockIdx.x * BN;
    int tid = threadIdx.x;
    int tx = tid & 15, ty = tid >> 4;

    // load-index helpers
    int a_row = tid >> 2;            // 0..63 (row within tile, +64 for 2nd)
    int a_k4  = (tid & 3) * 4;       // k offset (float4)
    int b_k   = tid >> 5;            // 0..7  (BT=false)
    int b_n   = (tid & 31) * 4;      // 0..124

    const float* Abase = A + (size_t)m0 * Kdim;

    float acc[8][8];
#pragma unroll
    for (int i = 0; i < 8; i++)
#pragma unroll
        for (int j = 0; j < 8; j++) acc[i][j] = 0.f;

    // ---- prologue: tile 0 -> smem buffer 0
    float4 pa[2], pb[2];
#pragma unroll
    for (int i = 0; i < 2; i++)
        pa[i] = *(const float4*)(Abase + (size_t)(a_row + i * 64) * Kdim + a_k4);
    if (BT) {
#pragma unroll
        for (int i = 0; i < 2; i++)
            pb[i] = *(const float4*)(Bp + (size_t)(n0 + a_row + i * 64) * Kdim + a_k4);
    } else {
#pragma unroll
        for (int i = 0; i < 2; i++)
            pb[i] = *(const float4*)(Bp + (size_t)(b_k + i * 8) * Ndim + n0 + b_n);
    }
#pragma unroll
    for (int i = 0; i < 2; i++) {
        int r = a_row + i * 64;
        As[0][a_k4 + 0][r] = pa[i].x; As[0][a_k4 + 1][r] = pa[i].y;
        As[0][a_k4 + 2][r] = pa[i].z; As[0][a_k4 + 3][r] = pa[i].w;
        if (BT) {
            Bs[0][a_k4 + 0][r] = pb[i].x; Bs[0][a_k4 + 1][r] = pb[i].y;
            Bs[0][a_k4 + 2][r] = pb[i].z; Bs[0][a_k4 + 3][r] = pb[i].w;
        } else {
            *(float4*)&Bs[0][b_k + i * 8][b_n] = pb[i];
        }
    }
    __syncthreads();

    int cur = 0;
    for (int k0 = 0; k0 < Kdim; k0 += BKT) {
        bool has_next = (k0 + BKT) < Kdim;
        if (has_next) {
            int kn = k0 + BKT;
#pragma unroll
            for (int i = 0; i < 2; i++)
                pa[i] = *(const float4*)(Abase + (size_t)(a_row + i * 64) * Kdim + kn + a_k4);
            if (BT) {
#pragma unroll
                for (int i = 0; i < 2; i++)
                    pb[i] = *(const float4*)(Bp + (size_t)(n0 + a_row + i * 64) * Kdim + kn + a_k4);
            } else {
#pragma unroll
                for (int i = 0; i < 2; i++)
                    pb[i] = *(const float4*)(Bp + (size_t)(kn + b_k + i * 8) * Ndim + n0 + b_n);
            }
        }
        // compute current tile (hides the LDGs above)
#pragma unroll
        for (int kk = 0; kk < BKT; kk++) {
            float a[8], bb[8];
            *(float4*)&a[0]  = *(const float4*)&As[cur][kk][ty * 4];
            *(float4*)&a[4]  = *(const float4*)&As[cur][kk][ty * 4 + 64];
            *(float4*)&bb[0] = *(const float4*)&Bs[cur][kk][tx * 4];
            *(float4*)&bb[4] = *(const float4*)&Bs[cur][kk][tx * 4 + 64];
#pragma unroll
            for (int i = 0; i < 8; i++)
#pragma unroll
                for (int j = 0; j < 8; j++)
                    acc[i][j] = fmaf(a[i], bb[j], acc[i][j]);
        }
        if (has_next) {
            int nxt = cur ^ 1;
#pragma unroll
            for (int i = 0; i < 2; i++) {
                int r = a_row + i * 64;
                As[nxt][a_k4 + 0][r] = pa[i].x; As[nxt][a_k4 + 1][r] = pa[i].y;
                As[nxt][a_k4 + 2][r] = pa[i].z; As[nxt][a_k4 + 3][r] = pa[i].w;
                if (BT) {
                    Bs[nxt][a_k4 + 0][r] = pb[i].x; Bs[nxt][a_k4 + 1][r] = pb[i].y;
                    Bs[nxt][a_k4 + 2][r] = pb[i].z; Bs[nxt][a_k4 + 3][r] = pb[i].w;
                } else {
                    *(float4*)&Bs[nxt][b_k + i * 8][b_n] = pb[i];
                }
            }
            __syncthreads();
            cur = nxt;
        }
    }

    // epilogue
#pragma unroll
    for (int i = 0; i < 8; i++) {
        int m = m0 + ty * 4 + (i & 3) + (i >> 2) * 64;
        float* crow = C + (size_t)m * Ndim;
#pragma unroll
        for (int jh = 0; jh < 2; jh++) {
            int n = n0 + tx * 4 + jh * 64;
            float4 v = make_float4(acc[i][jh * 4 + 0], acc[i][jh * 4 + 1],
                                   acc[i][jh * 4 + 2], acc[i][jh * 4 + 3]);
            if (bias) {
                v.x += bias[n]; v.y += bias[n + 1];
                v.z += bias[n + 2]; v.w += bias[n + 3];
            }
            *(float4*)(crow + n) = v;
        }
    }
}

// NOTE: acc row index i maps to matrix row ty*4 + (i&3) + (i>>2)*64, and the
// compute loop's a[i] was loaded from As[kk][ty*4 + ...] in the same order
// (a[0..3] = rows ty*4..ty*4+3, a[4..7] = rows ty*4+64..). Consistent.

// ---------------- launch -----------------------------------------------------
extern "C" void kernel_launch(void* const* d_in, const int* in_sizes, int n_in,
                              void* d_out, int out_size)
{
    const float* x     = (const float*)d_in[0];
    const float* basis = (const float*)d_in[1];
    const float* Wq    = (const float*)d_in[2];
    const float* bq    = (const float*)d_in[3];
    const float* Wk    = (const float*)d_in[4];
    const float* bk    = (const float*)d_in[5];
    const float* Wv    = (const float*)d_in[6];
    const float* bv    = (const float*)d_in[7];
    float* out = (float*)d_out;

    float *pv, *pp;
    cudaGetSymbolAddress((void**)&pv, g_v);
    cudaGetSymbolAddress((void**)&pp, g_p);

    // K1: fold basis into Q/K projections
    fold_kernel<<<dim3(4, 16), 256>>>(basis, Wq, bq, Wk, bk);

    // K2: kan_q, kan_k  [8192,16]
    kan_kernel<<<MTOK / 8, 256>>>(x);

    // K3: v = x @ Wv^T + bv   [8192,1024]
    sgemm_kernel<true><<<dim3(DIM / BN, MTOK / BM, 1), 256>>>(
        x, Wv, bv, pv, DIM, DIM, 0L, 0L, 0L);

    // K4a: S = kanq @ kank^T / 32   [4,2048,2048]
    score_kernel<<<dim3(SEQ / 128, SEQ / 128, NB), 256>>>();

    // K4b: row softmax in place
    softmax_kernel<<<MTOK, 256>>>();

    // K5: out = P @ v   batched [4] x [2048,2048]@[2048,1024]
    sgemm_kernel<false><<<dim3(DIM / BN, SEQ / BM, NB), 256>>>(
        pp, pv, nullptr, out,
        SEQ, DIM,
        (long)SEQ * SEQ, (long)SEQ * DIM, (long)SEQ * DIM);
}

// round 6
// speedup vs baseline: 2.5029x; 1.8245x over previous
#include <cuda_runtime.h>
#include <cuda_bf16.h>
#include <math.h>
#include <stdint.h>

#define DIM   1024
#define NUM_F 16
#define NB    4
#define SEQ   2048
#define MTOK  (NB * SEQ)   // 8192

// ======================= scratch (static device globals) ====================
__device__ float          g_p [MTOK * SEQ];      // fp32 scores (pre-softmax)
__device__ __nv_bfloat16  g_ph[MTOK * SEQ];      // softmax(P) hi
__device__ __nv_bfloat16  g_pl[MTOK * SEQ];      // softmax(P) lo
__device__ __nv_bfloat16  g_xh[MTOK * DIM];
__device__ __nv_bfloat16  g_xl[MTOK * DIM];
__device__ __nv_bfloat16  g_wh[DIM * DIM];
__device__ __nv_bfloat16  g_wl[DIM * DIM];
__device__ __nv_bfloat16  g_vth[MTOK * DIM];     // v^T  [NB][DIM][SEQ] hi
__device__ __nv_bfloat16  g_vtl[MTOK * DIM];     // v^T  lo
__device__ float g_kanq[MTOK * NUM_F];
__device__ float g_kank[MTOK * NUM_F];
__device__ float g_Cq[NUM_F * DIM];
__device__ float g_Ck[NUM_F * DIM];
__device__ float g_cq[NUM_F];
__device__ float g_ck[NUM_F];

// ======================= helpers ============================================
__device__ __forceinline__ uint32_t smem_u32(const void* p) {
    uint32_t a;
    asm("{ .reg .u64 t; cvta.to.shared.u64 t, %1; cvt.u32.u64 %0, t; }"
        : "=r"(a) : "l"(p));
    return a;
}
__device__ __forceinline__ void ldmx4(uint32_t* r, uint32_t addr) {
    asm volatile("ldmatrix.sync.aligned.m8n8.x4.shared.b16 {%0,%1,%2,%3}, [%4];"
        : "=r"(r[0]), "=r"(r[1]), "=r"(r[2]), "=r"(r[3]) : "r"(addr));
}
__device__ __forceinline__ void ldmx2(uint32_t* r, uint32_t addr) {
    asm volatile("ldmatrix.sync.aligned.m8n8.x2.shared.b16 {%0,%1}, [%2];"
        : "=r"(r[0]), "=r"(r[1]) : "r"(addr));
}
__device__ __forceinline__ void mma_bf16(float* c, const uint32_t* a, const uint32_t* b) {
    asm volatile("mma.sync.aligned.m16n8k16.row.col.f32.bf16.bf16.f32 "
        "{%0,%1,%2,%3}, {%4,%5,%6,%7}, {%8,%9}, {%0,%1,%2,%3};"
        : "+f"(c[0]), "+f"(c[1]), "+f"(c[2]), "+f"(c[3])
        : "r"(a[0]), "r"(a[1]), "r"(a[2]), "r"(a[3]), "r"(b[0]), "r"(b[1]));
}
__device__ __forceinline__ uint32_t pack2bf(float a, float b) {
    __nv_bfloat162 t = __floats2bfloat162_rn(a, b);
    return *(uint32_t*)&t;
}

// ======================= K1: fold basis into Wq/Wk ==========================
__global__ void fold_kernel(const float* __restrict__ basis,
                            const float* __restrict__ Wq, const float* __restrict__ bq,
                            const float* __restrict__ Wk, const float* __restrict__ bk)
{
    int d = blockIdx.x * blockDim.x + threadIdx.x;
    int f = blockIdx.y;
    float aq = 0.f, ak = 0.f;
    for (int e = 0; e < DIM; e++) {
        float be = basis[f * DIM + e];
        aq = fmaf(be, Wq[e * DIM + d], aq);
        ak = fmaf(be, Wk[e * DIM + d], ak);
    }
    g_Cq[f * DIM + d] = aq;
    g_Ck[f * DIM + d] = ak;
    if (blockIdx.x == 0 && threadIdx.x == 0) {
        float sq = 0.f, sk = 0.f;
        for (int e = 0; e < DIM; e++) {
            sq = fmaf(basis[f * DIM + e], bq[e], sq);
            sk = fmaf(basis[f * DIM + e], bk[e], sk);
        }
        g_cq[f] = sq;
        g_ck[f] = sk;
    }
}

// ======================= K2: kan projections ================================
__global__ void kan_kernel(const float* __restrict__ x)
{
    int warp = threadIdx.x >> 5;
    int lane = threadIdx.x & 31;
    int m = blockIdx.x * 8 + warp;
    float aq[NUM_F], ak[NUM_F];
#pragma unroll
    for (int f = 0; f < NUM_F; f++) { aq[f] = 0.f; ak[f] = 0.f; }
    const float* xr = x + (size_t)m * DIM;
    for (int d = lane; d < DIM; d += 32) {
        float xv = xr[d];
#pragma unroll
        for (int f = 0; f < NUM_F; f++) {
            aq[f] = fmaf(xv, g_Cq[f * DIM + d], aq[f]);
            ak[f] = fmaf(xv, g_Ck[f * DIM + d], ak[f]);
        }
    }
#pragma unroll
    for (int f = 0; f < NUM_F; f++) {
#pragma unroll
        for (int off = 16; off; off >>= 1) {
            aq[f] += __shfl_down_sync(0xffffffffu, aq[f], off);
            ak[f] += __shfl_down_sync(0xffffffffu, ak[f], off);
        }
    }
    if (lane == 0) {
#pragma unroll
        for (int f = 0; f < NUM_F; f++) {
            g_kanq[m * NUM_F + f] = aq[f] + g_cq[f];
            g_kank[m * NUM_F + f] = ak[f] + g_ck[f];
        }
    }
}

// ======================= split fp32 -> bf16 hi/lo ===========================
__global__ void split_kernel(const float* __restrict__ src,
                             __nv_bfloat16* __restrict__ hi,
                             __nv_bfloat16* __restrict__ lo)
{
    int i = blockIdx.x * blockDim.x + threadIdx.x;   // float4 index
    float4 v = ((const float4*)src)[i];
    float h0 = __bfloat162float(__float2bfloat16(v.x));
    float h1 = __bfloat162float(__float2bfloat16(v.y));
    float h2 = __bfloat162float(__float2bfloat16(v.z));
    float h3 = __bfloat162float(__float2bfloat16(v.w));
    ((uint2*)hi)[i] = make_uint2(pack2bf(h0, h1), pack2bf(h2, h3));
    ((uint2*)lo)[i] = make_uint2(pack2bf(v.x - h0, v.y - h1),
                                 pack2bf(v.z - h2, v.w - h3));
}

// ======================= K4a: rank-16 score GEMM ============================
__global__ __launch_bounds__(256) void score_kernel()
{
    __shared__ float Qs[NUM_F][128];
    __shared__ float Ks[NUM_F][128];
    int b  = blockIdx.z;
    int m0 = blockIdx.y * 128;
    int n0 = blockIdx.x * 128;
    int tid = threadIdx.x;

    const float* qg = g_kanq + ((size_t)b * SEQ + m0) * NUM_F;
    const float* kg = g_kank + ((size_t)b * SEQ + n0) * NUM_F;
#pragma unroll
    for (int it = 0; it < 2; it++) {
        int f4 = tid + it * 256;
        int m  = f4 >> 2;
        int k4 = (f4 & 3) * 4;
        float4 vq = ((const float4*)qg)[f4];
        float4 vk = ((const float4*)kg)[f4];
        Qs[k4 + 0][m] = vq.x; Qs[k4 + 1][m] = vq.y;
        Qs[k4 + 2][m] = vq.z; Qs[k4 + 3][m] = vq.w;
        Ks[k4 + 0][m] = vk.x; Ks[k4 + 1][m] = vk.y;
        Ks[k4 + 2][m] = vk.z; Ks[k4 + 3][m] = vk.w;
    }
    __syncthreads();

    int tx = tid & 15, ty = tid >> 4;
    float acc[8][8];
#pragma unroll
    for (int i = 0; i < 8; i++)
#pragma unroll
        for (int j = 0; j < 8; j++) acc[i][j] = 0.f;

#pragma unroll
    for (int kk = 0; kk < NUM_F; kk++) {
        float a[8], bb[8];
        *(float4*)&a[0]  = *(const float4*)&Qs[kk][ty * 4];
        *(float4*)&a[4]  = *(const float4*)&Qs[kk][ty * 4 + 64];
        *(float4*)&bb[0] = *(const float4*)&Ks[kk][tx * 4];
        *(float4*)&bb[4] = *(const float4*)&Ks[kk][tx * 4 + 64];
#pragma unroll
        for (int i = 0; i < 8; i++)
#pragma unroll
            for (int j = 0; j < 8; j++)
                acc[i][j] = fmaf(a[i], bb[j], acc[i][j]);
    }

    const float scale = 1.0f / 32.0f;
    float* pg = g_p + (size_t)b * SEQ * SEQ;
#pragma unroll
    for (int i = 0; i < 8; i++) {
        int m = m0 + ty * 4 + (i & 3) + (i >> 2) * 64;
        float* prow = pg + (size_t)m * SEQ + n0;
#pragma unroll
        for (int jh = 0; jh < 2; jh++) {
            int n = tx * 4 + jh * 64;
            float4 v = make_float4(acc[i][jh * 4 + 0] * scale, acc[i][jh * 4 + 1] * scale,
                                   acc[i][jh * 4 + 2] * scale, acc[i][jh * 4 + 3] * scale);
            *(float4*)(prow + n) = v;
        }
    }
}

// ======================= K4b: softmax -> bf16 split =========================
__global__ __launch_bounds__(256) void softmax_kernel()
{
    __shared__ float4 srow[SEQ / 4];
    __shared__ float red[8];
    int r = blockIdx.x;
    int tid = threadIdx.x;
    int lane = tid & 31, wid = tid >> 5;
    const float4* pr = (const float4*)(g_p + (size_t)r * SEQ);

    float lmax = -INFINITY;
#pragma unroll
    for (int it = 0; it < 2; it++) {
        int j = tid + it * 256;
        float4 v = pr[j];
        srow[j] = v;
        lmax = fmaxf(lmax, fmaxf(fmaxf(v.x, v.y), fmaxf(v.z, v.w)));
    }
#pragma unroll
    for (int off = 16; off; off >>= 1)
        lmax = fmaxf(lmax, __shfl_xor_sync(0xffffffffu, lmax, off));
    if (lane == 0) red[wid] = lmax;
    __syncthreads();
    float bmax = red[0];
#pragma unroll
    for (int w = 1; w < 8; w++) bmax = fmaxf(bmax, red[w]);

    float lsum = 0.f;
#pragma unroll
    for (int it = 0; it < 2; it++) {
        int j = tid + it * 256;
        float4 v = srow[j];
        v.x = __expf(v.x - bmax); v.y = __expf(v.y - bmax);
        v.z = __expf(v.z - bmax); v.w = __expf(v.w - bmax);
        srow[j] = v;
        lsum += v.x + v.y + v.z + v.w;
    }
#pragma unroll
    for (int off = 16; off; off >>= 1)
        lsum += __shfl_xor_sync(0xffffffffu, lsum, off);
    __syncthreads();
    if (lane == 0) red[wid] = lsum;
    __syncthreads();
    float bsum = 0.f;
#pragma unroll
    for (int w = 0; w < 8; w++) bsum += red[w];
    float inv = 1.0f / bsum;

    uint2* ph = (uint2*)(g_ph + (size_t)r * SEQ);
    uint2* pl = (uint2*)(g_pl + (size_t)r * SEQ);
#pragma unroll
    for (int it = 0; it < 2; it++) {
        int j = tid + it * 256;
        float4 v = srow[j];
        v.x *= inv; v.y *= inv; v.z *= inv; v.w *= inv;
        float h0 = __bfloat162float(__float2bfloat16(v.x));
        float h1 = __bfloat162float(__float2bfloat16(v.y));
        float h2 = __bfloat162float(__float2bfloat16(v.z));
        float h3 = __bfloat162float(__float2bfloat16(v.w));
        ph[j] = make_uint2(pack2bf(h0, h1), pack2bf(h2, h3));
        pl[j] = make_uint2(pack2bf(v.x - h0, v.y - h1), pack2bf(v.z - h2, v.w - h3));
    }
}

// ======================= mma.sync GEMM: C = A @ B^T (bf16 split) ============
// Block 128x128, 8 warps each 64x32. BK=32. smem stride 40 bf16 (80B):
// ldmatrix row addrs hit r*5 mod 8 -> all distinct 16B groups, conflict-free.
// TRANS=true : C written transposed as bf16 hi/lo into g_vth/g_vtl (+bias)
// TRANS=false: C written fp32 row-major [m][Ndim] to Cout
#define MSTRIDE 40
#define TILE_B  (128 * MSTRIDE * 2)     // 10240 B
#define MM_SMEM (8 * TILE_B)            // 81920 B (also covers 128*132*4 epi)

template <bool TRANS>
__global__ __launch_bounds__(256, 1) void mma_gemm(
    const __nv_bfloat16* __restrict__ Ah_, const __nv_bfloat16* __restrict__ Al_,
    const __nv_bfloat16* __restrict__ Bh_, const __nv_bfloat16* __restrict__ Bl_,
    const float* __restrict__ bias, float* __restrict__ Cout,
    int Kdim, int Ndim, long sA, long sB, long sC)
{
    extern __shared__ char smem[];
    const uint32_t sb = smem_u32(smem);
    const int tid  = threadIdx.x;
    const int lane = tid & 31, wid = tid >> 5;
    const int warp_m = wid & 1, warp_n = wid >> 1;
    const int z  = blockIdx.z;
    const int m0 = blockIdx.y * 128, n0 = blockIdx.x * 128;

    const __nv_bfloat16* pAh = Ah_ + (size_t)z * sA;
    const __nv_bfloat16* pAl = Al_ + (size_t)z * sA;
    const __nv_bfloat16* pBh = Bh_ + (size_t)z * sB;
    const __nv_bfloat16* pBl = Bl_ + (size_t)z * sB;

    // global-load geometry: 2 16B chunks per tile per thread
    const int c1 = tid + 256;
    const int ar0 = tid >> 2, ak0 = (tid & 3) * 8;
    const int ar1 = c1 >> 2,  ak1 = (c1 & 3) * 8;
    const size_t gA0 = (size_t)(m0 + ar0) * Kdim + ak0;
    const size_t gA1 = (size_t)(m0 + ar1) * Kdim + ak1;
    const size_t gB0 = (size_t)(n0 + ar0) * Kdim + ak0;
    const size_t gB1 = (size_t)(n0 + ar1) * Kdim + ak1;
    const uint32_t s0 = (uint32_t)(ar0 * MSTRIDE + ak0) * 2;
    const uint32_t s1 = (uint32_t)(ar1 * MSTRIDE + ak1) * 2;

    float acc[4][4][4];
#pragma unroll
    for (int mi = 0; mi < 4; mi++)
#pragma unroll
        for (int ni = 0; ni < 4; ni++)
#pragma unroll
            for (int rr = 0; rr < 4; rr++) acc[mi][ni][rr] = 0.f;

    uint4 rg[8];
    const int T = Kdim >> 5;

#define LOADG(K0) do {                                                 \
        rg[0] = *(const uint4*)(pAh + gA0 + (K0));                     \
        rg[1] = *(const uint4*)(pAh + gA1 + (K0));                     \
        rg[2] = *(const uint4*)(pAl + gA0 + (K0));                     \
        rg[3] = *(const uint4*)(pAl + gA1 + (K0));                     \
        rg[4] = *(const uint4*)(pBh + gB0 + (K0));                     \
        rg[5] = *(const uint4*)(pBh + gB1 + (K0));                     \
        rg[6] = *(const uint4*)(pBl + gB0 + (K0));                     \
        rg[7] = *(const uint4*)(pBl + gB1 + (K0));                     \
    } while (0)

#define STORES(S) do {                                                 \
        char* base = smem + (S) * 4 * TILE_B;                          \
        *(uint4*)(base + s0)              = rg[0];                     \
        *(uint4*)(base + s1)              = rg[1];                     \
        *(uint4*)(base + TILE_B + s0)     = rg[2];                     \
        *(uint4*)(base + TILE_B + s1)     = rg[3];                     \
        *(uint4*)(base + 2 * TILE_B + s0) = rg[4];                     \
        *(uint4*)(base + 2 * TILE_B + s1) = rg[5];                     \
        *(uint4*)(base + 3 * TILE_B + s0) = rg[6];                     \
        *(uint4*)(base + 3 * TILE_B + s1) = rg[7];                     \
    } while (0)

    const int arow = warp_m * 64 + (lane & 15);
    const int acol = (lane >> 4) * 8;
    const int brow = warp_n * 32 + (lane & 7);
    const int bcol = ((lane >> 3) & 1) * 8;

    LOADG(0);
    STORES(0);
    __syncthreads();

    for (int t = 0; t < T; t++) {
        if (t + 1 < T) LOADG((t + 1) << 5);
        uint32_t base = sb + (uint32_t)(t & 1) * 4 * TILE_B;
#pragma unroll
        for (int kk = 0; kk < 32; kk += 16) {
            uint32_t ah[4][4], al[4][4], bh[4][2], bl[4][2];
#pragma unroll
            for (int mi = 0; mi < 4; mi++) {
                uint32_t ad = (uint32_t)(((arow + mi * 16) * MSTRIDE + kk + acol) * 2);
                ldmx4(ah[mi], base + ad);
                ldmx4(al[mi], base + TILE_B + ad);
            }
#pragma unroll
            for (int ni = 0; ni < 4; ni++) {
                uint32_t bd = (uint32_t)(((brow + ni * 8) * MSTRIDE + kk + bcol) * 2);
                ldmx2(bh[ni], base + 2 * TILE_B + bd);
                ldmx2(bl[ni], base + 3 * TILE_B + bd);
            }
#pragma unroll
            for (int mi = 0; mi < 4; mi++)
#pragma unroll
                for (int ni = 0; ni < 4; ni++) {
                    mma_bf16(acc[mi][ni], ah[mi], bh[ni]);
                    mma_bf16(acc[mi][ni], ah[mi], bl[ni]);
                    mma_bf16(acc[mi][ni], al[mi], bh[ni]);
                }
        }
        if (t + 1 < T) {
            STORES((t + 1) & 1);
            __syncthreads();
        }
    }
#undef LOADG
#undef STORES

    // ---------------- epilogue ----------------
    if (TRANS) {
        __syncthreads();                 // smem tiles no longer needed
        float* st = (float*)smem;        // [128 n][132]
#pragma unroll
        for (int mi = 0; mi < 4; mi++) {
            int rowl = warp_m * 64 + mi * 16 + (lane >> 2);
#pragma unroll
            for (int ni = 0; ni < 4; ni++) {
                int coll = warp_n * 32 + ni * 8 + (lane & 3) * 2;
                float b0 = bias[n0 + coll], b1 = bias[n0 + coll + 1];
                st[coll * 132 + rowl]           = acc[mi][ni][0] + b0;
                st[(coll + 1) * 132 + rowl]     = acc[mi][ni][1] + b1;
                st[coll * 132 + rowl + 8]       = acc[mi][ni][2] + b0;
                st[(coll + 1) * 132 + rowl + 8] = acc[mi][ni][3] + b1;
            }
        }
        __syncthreads();
        int bz  = m0 >> 11;
        int m0s = m0 & (SEQ - 1);
        for (int w = tid; w < 128 * 64; w += 256) {
            int d = w >> 6, mp = w & 63;
            float v0 = st[d * 132 + mp * 2];
            float v1 = st[d * 132 + mp * 2 + 1];
            float h0 = __bfloat162float(__float2bfloat16(v0));
            float h1 = __bfloat162float(__float2bfloat16(v1));
            size_t idx = (((size_t)(bz * DIM + n0 + d) * SEQ + m0s) >> 1) + mp;
            ((uint32_t*)g_vth)[idx] = pack2bf(h0, h1);
            ((uint32_t*)g_vtl)[idx] = pack2bf(v0 - h0, v1 - h1);
        }
    } else {
        float* C = Cout + (size_t)z * sC;
#pragma unroll
        for (int mi = 0; mi < 4; mi++) {
            int row = m0 + warp_m * 64 + mi * 16 + (lane >> 2);
#pragma unroll
            for (int ni = 0; ni < 4; ni++) {
                int col = n0 + warp_n * 32 + ni * 8 + (lane & 3) * 2;
                *(float2*)&C[(size_t)row * Ndim + col] =
                    make_float2(acc[mi][ni][0], acc[mi][ni][1]);
                *(float2*)&C[(size_t)(row + 8) * Ndim + col] =
                    make_float2(acc[mi][ni][2], acc[mi][ni][3]);
            }
        }
    }
}

// ======================= launch =============================================
extern "C" void kernel_launch(void* const* d_in, const int* in_sizes, int n_in,
                              void* d_out, int out_size)
{
    const float* x     = (const float*)d_in[0];
    const float* basis = (const float*)d_in[1];
    const float* Wq    = (const float*)d_in[2];
    const float* bq    = (const float*)d_in[3];
    const float* Wk    = (const float*)d_in[4];
    const float* bk    = (const float*)d_in[5];
    const float* Wv    = (const float*)d_in[6];
    const float* bv    = (const float*)d_in[7];
    float* out = (float*)d_out;

    __nv_bfloat16 *pxh, *pxl, *pwh, *pwl, *pph, *ppl, *pvth, *pvtl;
    cudaGetSymbolAddress((void**)&pxh, g_xh);
    cudaGetSymbolAddress((void**)&pxl, g_xl);
    cudaGetSymbolAddress((void**)&pwh, g_wh);
    cudaGetSymbolAddress((void**)&pwl, g_wl);
    cudaGetSymbolAddress((void**)&pph, g_ph);
    cudaGetSymbolAddress((void**)&ppl, g_pl);
    cudaGetSymbolAddress((void**)&pvth, g_vth);
    cudaGetSymbolAddress((void**)&pvtl, g_vtl);

    cudaFuncSetAttribute(mma_gemm<true>,  cudaFuncAttributeMaxDynamicSharedMemorySize, MM_SMEM);
    cudaFuncSetAttribute(mma_gemm<false>, cudaFuncAttributeMaxDynamicSharedMemorySize, MM_SMEM);

    // splits
    split_kernel<<<MTOK * DIM / 4 / 256, 256>>>(x, pxh, pxl);
    split_kernel<<<DIM * DIM / 4 / 256, 256>>>(Wv, pwh, pwl);

    // fold + kan
    fold_kernel<<<dim3(4, 16), 256>>>(basis, Wq, bq, Wk, bk);
    kan_kernel<<<MTOK / 8, 256>>>(x);

    // K3: v = x @ Wv^T + bv  -> vT (bf16 split), mma.sync
    mma_gemm<true><<<dim3(DIM / 128, MTOK / 128, 1), 256, MM_SMEM>>>(
        pxh, pxl, pwh, pwl, bv, nullptr, DIM, DIM, 0L, 0L, 0L);

    // K4: scores + softmax (-> bf16 split P)
    score_kernel<<<dim3(SEQ / 128, SEQ / 128, NB), 256>>>();
    softmax_kernel<<<MTOK, 256>>>();

    // K5: out = P @ v  (= P @ (vT)^T), mma.sync
    mma_gemm<false><<<dim3(DIM / 128, SEQ / 128, NB), 256, MM_SMEM>>>(
        pph, ppl, pvth, pvtl, nullptr, out, SEQ, DIM,
        (long)SEQ * SEQ, (long)DIM * SEQ, (long)SEQ * DIM);
}

// round 7
// speedup vs baseline: 3.0069x; 1.2014x over previous
#include <cuda_runtime.h>
#include <cuda_bf16.h>
#include <math.h>
#include <stdint.h>

#define DIM   1024
#define NUM_F 16
#define NB    4
#define SEQ   2048
#define MTOK  (NB * SEQ)   // 8192

// ======================= scratch (static device globals) ====================
__device__ float          g_p [MTOK * SEQ];      // fp32 scores (pre-softmax)
__device__ __nv_bfloat16  g_ph[MTOK * SEQ];      // softmax(P) hi
__device__ __nv_bfloat16  g_pl[MTOK * SEQ];      // softmax(P) lo
__device__ __nv_bfloat16  g_xh[MTOK * DIM];
__device__ __nv_bfloat16  g_xl[MTOK * DIM];
__device__ __nv_bfloat16  g_wh[DIM * DIM];
__device__ __nv_bfloat16  g_wl[DIM * DIM];
__device__ __nv_bfloat16  g_vth[MTOK * DIM];     // v^T  [NB][DIM][SEQ] hi
__device__ __nv_bfloat16  g_vtl[MTOK * DIM];     // v^T  lo
__device__ float g_kanq[MTOK * NUM_F];
__device__ float g_kank[MTOK * NUM_F];
__device__ __nv_bfloat16 g_Ch[32 * DIM];         // folded C (rows 0-15 q, 16-31 k) hi
__device__ __nv_bfloat16 g_Cl[32 * DIM];         // lo
__device__ float g_cq[NUM_F];
__device__ float g_ck[NUM_F];

// ======================= helpers ============================================
__device__ __forceinline__ uint32_t smem_u32(const void* p) {
    uint32_t a;
    asm("{ .reg .u64 t; cvta.to.shared.u64 t, %1; cvt.u32.u64 %0, t; }"
        : "=r"(a) : "l"(p));
    return a;
}
__device__ __forceinline__ void ldmx4(uint32_t* r, uint32_t addr) {
    asm volatile("ldmatrix.sync.aligned.m8n8.x4.shared.b16 {%0,%1,%2,%3}, [%4];"
        : "=r"(r[0]), "=r"(r[1]), "=r"(r[2]), "=r"(r[3]) : "r"(addr));
}
__device__ __forceinline__ void ldmx2(uint32_t* r, uint32_t addr) {
    asm volatile("ldmatrix.sync.aligned.m8n8.x2.shared.b16 {%0,%1}, [%2];"
        : "=r"(r[0]), "=r"(r[1]) : "r"(addr));
}
__device__ __forceinline__ void mma_bf16(float* c, const uint32_t* a, const uint32_t* b) {
    asm volatile("mma.sync.aligned.m16n8k16.row.col.f32.bf16.bf16.f32 "
        "{%0,%1,%2,%3}, {%4,%5,%6,%7}, {%8,%9}, {%0,%1,%2,%3};"
        : "+f"(c[0]), "+f"(c[1]), "+f"(c[2]), "+f"(c[3])
        : "r"(a[0]), "r"(a[1]), "r"(a[2]), "r"(a[3]), "r"(b[0]), "r"(b[1]));
}
__device__ __forceinline__ uint32_t pack2bf(float a, float b) {
    __nv_bfloat162 t = __floats2bfloat162_rn(a, b);
    return *(uint32_t*)&t;
}
// exp via FMA pipe (no MUFU): exp(x) = 2^(x*log2e), degree-6 Taylor on frac.
__device__ __forceinline__ float fexp(float x) {
    float t = fmaxf(x * 1.4426950408889634f, -120.f);
    float fl = floorf(t);
    float f = t - fl;
    float p = 1.5403530e-4f;
    p = fmaf(p, f, 1.3333558e-3f);
    p = fmaf(p, f, 9.6181291e-3f);
    p = fmaf(p, f, 5.5504109e-2f);
    p = fmaf(p, f, 2.4022651e-1f);
    p = fmaf(p, f, 6.9314718e-1f);
    p = fmaf(p, f, 1.0f);
    int i = (int)fl;
    return p * __int_as_float((uint32_t)(i + 127) << 23);
}

// ======================= K1: fold basis into Wq/Wk (bf16 split out) =========
// f = blockIdx.y in 0..31: rows 0-15 from Wq, 16-31 from Wk.
__global__ void fold_kernel(const float* __restrict__ basis,
                            const float* __restrict__ Wq, const float* __restrict__ bq,
                            const float* __restrict__ Wk, const float* __restrict__ bk)
{
    int d = blockIdx.x * blockDim.x + threadIdx.x;
    int f = blockIdx.y;
    const float* W  = (f < 16) ? Wq : Wk;
    const float* br = basis + (size_t)(f & 15) * DIM;
    float a = 0.f;
    for (int e = 0; e < DIM; e++)
        a = fmaf(br[e], W[(size_t)e * DIM + d], a);
    float h = __bfloat162float(__float2bfloat16(a));
    g_Ch[f * DIM + d] = __float2bfloat16(h);
    g_Cl[f * DIM + d] = __float2bfloat16(a - h);
    if (blockIdx.x == 0 && threadIdx.x == 0) {
        const float* bb = (f < 16) ? bq : bk;
        float s = 0.f;
        for (int e = 0; e < DIM; e++) s = fmaf(br[e], bb[e], s);
        if (f < 16) g_cq[f] = s; else g_ck[f - 16] = s;
    }
}

// ======================= split fp32 -> bf16 hi/lo ===========================
__global__ void split_kernel(const float* __restrict__ src,
                             __nv_bfloat16* __restrict__ hi,
                             __nv_bfloat16* __restrict__ lo)
{
    int i = blockIdx.x * blockDim.x + threadIdx.x;   // float4 index
    float4 v = ((const float4*)src)[i];
    float h0 = __bfloat162float(__float2bfloat16(v.x));
    float h1 = __bfloat162float(__float2bfloat16(v.y));
    float h2 = __bfloat162float(__float2bfloat16(v.z));
    float h3 = __bfloat162float(__float2bfloat16(v.w));
    ((uint2*)hi)[i] = make_uint2(pack2bf(h0, h1), pack2bf(h2, h3));
    ((uint2*)lo)[i] = make_uint2(pack2bf(v.x - h0, v.y - h1),
                                 pack2bf(v.z - h2, v.w - h3));
}

// ======================= K2: kan via mma.sync  [8192,32] = x @ Ccomb^T ======
// Block: 128 rows, 8 warps each 16x32. BK=32, single-buffered smem.
#define KSTR 40
__global__ __launch_bounds__(256) void kan_mma_kernel()
{
    __shared__ __align__(16) __nv_bfloat16 sXh[128 * KSTR];
    __shared__ __align__(16) __nv_bfloat16 sXl[128 * KSTR];
    __shared__ __align__(16) __nv_bfloat16 sCh[32 * KSTR];
    __shared__ __align__(16) __nv_bfloat16 sCl[32 * KSTR];
    const int tid = threadIdx.x;
    const int lane = tid & 31, wid = tid >> 5;
    const int m0 = blockIdx.x * 128;

    const uint32_t uXh = smem_u32(sXh), uXl = smem_u32(sXl);
    const uint32_t uCh = smem_u32(sCh), uCl = smem_u32(sCl);

    // X load geometry: 512 chunks (16B) per half, 2 per thread
    const int xc0 = tid, xc1 = tid + 256;
    const int xr0 = xc0 >> 2, xk0 = (xc0 & 3) * 8;
    const int xr1 = xc1 >> 2, xk1 = (xc1 & 3) * 8;
    const uint32_t xs0 = (uint32_t)(xr0 * KSTR + xk0) * 2;
    const uint32_t xs1 = (uint32_t)(xr1 * KSTR + xk1) * 2;
    // C load: 128 chunks per half; tid<128 -> hi, else lo
    const int cc = tid & 127;
    const int cr = cc >> 2, ck = (cc & 3) * 8;
    const uint32_t cs = (uint32_t)(cr * KSTR + ck) * 2;

    float acc[4][4];
#pragma unroll
    for (int ni = 0; ni < 4; ni++)
#pragma unroll
        for (int rr = 0; rr < 4; rr++) acc[ni][rr] = 0.f;

    const int arow = wid * 16 + (lane & 15);
    const int acol = (lane >> 4) * 8;
    const int brow = lane & 7;
    const int bcol = ((lane >> 3) & 1) * 8;

    for (int t = 0; t < DIM / 32; t++) {
        int k0 = t * 32;
        if (t > 0) __syncthreads();
        *(uint4*)((char*)sXh + xs0) = *(const uint4*)(g_xh + (size_t)(m0 + xr0) * DIM + k0 + xk0);
        *(uint4*)((char*)sXh + xs1) = *(const uint4*)(g_xh + (size_t)(m0 + xr1) * DIM + k0 + xk1);
        *(uint4*)((char*)sXl + xs0) = *(const uint4*)(g_xl + (size_t)(m0 + xr0) * DIM + k0 + xk0);
        *(uint4*)((char*)sXl + xs1) = *(const uint4*)(g_xl + (size_t)(m0 + xr1) * DIM + k0 + xk1);
        if (tid < 128)
            *(uint4*)((char*)sCh + cs) = *(const uint4*)(g_Ch + (size_t)cr * DIM + k0 + ck);
        else
            *(uint4*)((char*)sCl + cs) = *(const uint4*)(g_Cl + (size_t)cr * DIM + k0 + ck);
        __syncthreads();
#pragma unroll
        for (int kk = 0; kk < 32; kk += 16) {
            uint32_t ah[4], al[4], bh[4][2], bl[4][2];
            uint32_t ad = (uint32_t)((arow * KSTR + kk + acol) * 2);
            ldmx4(ah, uXh + ad);
            ldmx4(al, uXl + ad);
#pragma unroll
            for (int ni = 0; ni < 4; ni++) {
                uint32_t bd = (uint32_t)(((brow + ni * 8) * KSTR + kk + bcol) * 2);
                ldmx2(bh[ni], uCh + bd);
                ldmx2(bl[ni], uCl + bd);
            }
#pragma unroll
            for (int ni = 0; ni < 4; ni++) {
                mma_bf16(acc[ni], ah, bh[ni]);
                mma_bf16(acc[ni], ah, bl[ni]);
                mma_bf16(acc[ni], al, bh[ni]);
            }
        }
    }

    // epilogue: add bias, scatter to g_kanq / g_kank
    int r0 = m0 + wid * 16 + (lane >> 2);
#pragma unroll
    for (int ni = 0; ni < 4; ni++) {
        int col = ni * 8 + (lane & 3) * 2;
#pragma unroll
        for (int cdx = 0; cdx < 2; cdx++) {
            int c = col + cdx;
            float bias = (c < 16) ? g_cq[c] : g_ck[c - 16];
            float* dst = (c < 16) ? g_kanq : g_kank;
            int f = c & 15;
            dst[(size_t)r0 * NUM_F + f]       = acc[ni][cdx]     + bias;
            dst[(size_t)(r0 + 8) * NUM_F + f] = acc[ni][cdx + 2] + bias;
        }
    }
}

// ======================= K4a: rank-16 score GEMM ============================
__global__ __launch_bounds__(256) void score_kernel()
{
    __shared__ float Qs[NUM_F][128];
    __shared__ float Ks[NUM_F][128];
    int b  = blockIdx.z;
    int m0 = blockIdx.y * 128;
    int n0 = blockIdx.x * 128;
    int tid = threadIdx.x;

    const float* qg = g_kanq + ((size_t)b * SEQ + m0) * NUM_F;
    const float* kg = g_kank + ((size_t)b * SEQ + n0) * NUM_F;
#pragma unroll
    for (int it = 0; it < 2; it++) {
        int f4 = tid + it * 256;
        int m  = f4 >> 2;
        int k4 = (f4 & 3) * 4;
        float4 vq = ((const float4*)qg)[f4];
        float4 vk = ((const float4*)kg)[f4];
        Qs[k4 + 0][m] = vq.x; Qs[k4 + 1][m] = vq.y;
        Qs[k4 + 2][m] = vq.z; Qs[k4 + 3][m] = vq.w;
        Ks[k4 + 0][m] = vk.x; Ks[k4 + 1][m] = vk.y;
        Ks[k4 + 2][m] = vk.z; Ks[k4 + 3][m] = vk.w;
    }
    __syncthreads();

    int tx = tid & 15, ty = tid >> 4;
    float acc[8][8];
#pragma unroll
    for (int i = 0; i < 8; i++)
#pragma unroll
        for (int j = 0; j < 8; j++) acc[i][j] = 0.f;

#pragma unroll
    for (int kk = 0; kk < NUM_F; kk++) {
        float a[8], bb[8];
        *(float4*)&a[0]  = *(const float4*)&Qs[kk][ty * 4];
        *(float4*)&a[4]  = *(const float4*)&Qs[kk][ty * 4 + 64];
        *(float4*)&bb[0] = *(const float4*)&Ks[kk][tx * 4];
        *(float4*)&bb[4] = *(const float4*)&Ks[kk][tx * 4 + 64];
#pragma unroll
        for (int i = 0; i < 8; i++)
#pragma unroll
            for (int j = 0; j < 8; j++)
                acc[i][j] = fmaf(a[i], bb[j], acc[i][j]);
    }

    const float scale = 1.0f / 32.0f;
    float* pg = g_p + (size_t)b * SEQ * SEQ;
#pragma unroll
    for (int i = 0; i < 8; i++) {
        int m = m0 + ty * 4 + (i & 3) + (i >> 2) * 64;
        float* prow = pg + (size_t)m * SEQ + n0;
#pragma unroll
        for (int jh = 0; jh < 2; jh++) {
            int n = tx * 4 + jh * 64;
            float4 v = make_float4(acc[i][jh * 4 + 0] * scale, acc[i][jh * 4 + 1] * scale,
                                   acc[i][jh * 4 + 2] * scale, acc[i][jh * 4 + 3] * scale);
            *(float4*)(prow + n) = v;
        }
    }
}

// ======================= K4b: softmax -> bf16 split (FMA exp) ===============
__global__ __launch_bounds__(256) void softmax_kernel()
{
    __shared__ float4 srow[SEQ / 4];
    __shared__ float red[8];
    int r = blockIdx.x;
    int tid = threadIdx.x;
    int lane = tid & 31, wid = tid >> 5;
    const float4* pr = (const float4*)(g_p + (size_t)r * SEQ);

    float lmax = -INFINITY;
#pragma unroll
    for (int it = 0; it < 2; it++) {
        int j = tid + it * 256;
        float4 v = pr[j];
        srow[j] = v;
        lmax = fmaxf(lmax, fmaxf(fmaxf(v.x, v.y), fmaxf(v.z, v.w)));
    }
#pragma unroll
    for (int off = 16; off; off >>= 1)
        lmax = fmaxf(lmax, __shfl_xor_sync(0xffffffffu, lmax, off));
    if (lane == 0) red[wid] = lmax;
    __syncthreads();
    float bmax = red[0];
#pragma unroll
    for (int w = 1; w < 8; w++) bmax = fmaxf(bmax, red[w]);

    float lsum = 0.f;
#pragma unroll
    for (int it = 0; it < 2; it++) {
        int j = tid + it * 256;
        float4 v = srow[j];
        v.x = fexp(v.x - bmax); v.y = fexp(v.y - bmax);
        v.z = fexp(v.z - bmax); v.w = fexp(v.w - bmax);
        srow[j] = v;
        lsum += v.x + v.y + v.z + v.w;
    }
#pragma unroll
    for (int off = 16; off; off >>= 1)
        lsum += __shfl_xor_sync(0xffffffffu, lsum, off);
    __syncthreads();
    if (lane == 0) red[wid] = lsum;
    __syncthreads();
    float bsum = 0.f;
#pragma unroll
    for (int w = 0; w < 8; w++) bsum += red[w];
    float inv = 1.0f / bsum;

    uint2* ph = (uint2*)(g_ph + (size_t)r * SEQ);
    uint2* pl = (uint2*)(g_pl + (size_t)r * SEQ);
#pragma unroll
    for (int it = 0; it < 2; it++) {
        int j = tid + it * 256;
        float4 v = srow[j];
        v.x *= inv; v.y *= inv; v.z *= inv; v.w *= inv;
        float h0 = __bfloat162float(__float2bfloat16(v.x));
        float h1 = __bfloat162float(__float2bfloat16(v.y));
        float h2 = __bfloat162float(__float2bfloat16(v.z));
        float h3 = __bfloat162float(__float2bfloat16(v.w));
        ph[j] = make_uint2(pack2bf(h0, h1), pack2bf(h2, h3));
        pl[j] = make_uint2(pack2bf(v.x - h0, v.y - h1), pack2bf(v.z - h2, v.w - h3));
    }
}

// ======================= mma.sync GEMM: C = A @ B^T (bf16 split) ============
// Block 128x128, 8 warps each 64x32. BK=32. smem stride 40 bf16 (80B).
// TRANS=true : C written transposed as bf16 hi/lo into g_vth/g_vtl (+bias)
// TRANS=false: C written fp32 row-major [m][Ndim] to Cout
#define MSTRIDE 40
#define TILE_B  (128 * MSTRIDE * 2)     // 10240 B
#define MM_SMEM (8 * TILE_B)            // 81920 B (also covers 128*132*4 epi)

template <bool TRANS>
__global__ __launch_bounds__(256, 1) void mma_gemm(
    const __nv_bfloat16* __restrict__ Ah_, const __nv_bfloat16* __restrict__ Al_,
    const __nv_bfloat16* __restrict__ Bh_, const __nv_bfloat16* __restrict__ Bl_,
    const float* __restrict__ bias, float* __restrict__ Cout,
    int Kdim, int Ndim, long sA, long sB, long sC)
{
    extern __shared__ char smem[];
    const uint32_t sb = smem_u32(smem);
    const int tid  = threadIdx.x;
    const int lane = tid & 31, wid = tid >> 5;
    const int warp_m = wid & 1, warp_n = wid >> 1;
    const int z  = blockIdx.z;
    const int m0 = blockIdx.y * 128, n0 = blockIdx.x * 128;

    const __nv_bfloat16* pAh = Ah_ + (size_t)z * sA;
    const __nv_bfloat16* pAl = Al_ + (size_t)z * sA;
    const __nv_bfloat16* pBh = Bh_ + (size_t)z * sB;
    const __nv_bfloat16* pBl = Bl_ + (size_t)z * sB;

    const int c1 = tid + 256;
    const int ar0 = tid >> 2, ak0 = (tid & 3) * 8;
    const int ar1 = c1 >> 2,  ak1 = (c1 & 3) * 8;
    const size_t gA0 = (size_t)(m0 + ar0) * Kdim + ak0;
    const size_t gA1 = (size_t)(m0 + ar1) * Kdim + ak1;
    const size_t gB0 = (size_t)(n0 + ar0) * Kdim + ak0;
    const size_t gB1 = (size_t)(n0 + ar1) * Kdim + ak1;
    const uint32_t s0 = (uint32_t)(ar0 * MSTRIDE + ak0) * 2;
    const uint32_t s1 = (uint32_t)(ar1 * MSTRIDE + ak1) * 2;

    float acc[4][4][4];
#pragma unroll
    for (int mi = 0; mi < 4; mi++)
#pragma unroll
        for (int ni = 0; ni < 4; ni++)
#pragma unroll
            for (int rr = 0; rr < 4; rr++) acc[mi][ni][rr] = 0.f;

    uint4 rg[8];
    const int T = Kdim >> 5;

#define LOADG(K0) do {                                                 \
        rg[0] = *(const uint4*)(pAh + gA0 + (K0));                     \
        rg[1] = *(const uint4*)(pAh + gA1 + (K0));                     \
        rg[2] = *(const uint4*)(pAl + gA0 + (K0));                     \
        rg[3] = *(const uint4*)(pAl + gA1 + (K0));                     \
        rg[4] = *(const uint4*)(pBh + gB0 + (K0));                     \
        rg[5] = *(const uint4*)(pBh + gB1 + (K0));                     \
        rg[6] = *(const uint4*)(pBl + gB0 + (K0));                     \
        rg[7] = *(const uint4*)(pBl + gB1 + (K0));                     \
    } while (0)

#define STORES(S) do {                                                 \
        char* base = smem + (S) * 4 * TILE_B;                          \
        *(uint4*)(base + s0)              = rg[0];                     \
        *(uint4*)(base + s1)              = rg[1];                     \
        *(uint4*)(base + TILE_B + s0)     = rg[2];                     \
        *(uint4*)(base + TILE_B + s1)     = rg[3];                     \
        *(uint4*)(base + 2 * TILE_B + s0) = rg[4];                     \
        *(uint4*)(base + 2 * TILE_B + s1) = rg[5];                     \
        *(uint4*)(base + 3 * TILE_B + s0) = rg[6];                     \
        *(uint4*)(base + 3 * TILE_B + s1) = rg[7];                     \
    } while (0)

    const int arow = warp_m * 64 + (lane & 15);
    const int acol = (lane >> 4) * 8;
    const int brow = warp_n * 32 + (lane & 7);
    const int bcol = ((lane >> 3) & 1) * 8;

    LOADG(0);
    STORES(0);
    __syncthreads();

    for (int t = 0; t < T; t++) {
        if (t + 1 < T) LOADG((t + 1) << 5);
        uint32_t base = sb + (uint32_t)(t & 1) * 4 * TILE_B;
#pragma unroll
        for (int kk = 0; kk < 32; kk += 16) {
            uint32_t ah[4][4], al[4][4], bh[4][2], bl[4][2];
#pragma unroll
            for (int mi = 0; mi < 4; mi++) {
                uint32_t ad = (uint32_t)(((arow + mi * 16) * MSTRIDE + kk + acol) * 2);
                ldmx4(ah[mi], base + ad);
                ldmx4(al[mi], base + TILE_B + ad);
            }
#pragma unroll
            for (int ni = 0; ni < 4; ni++) {
                uint32_t bd = (uint32_t)(((brow + ni * 8) * MSTRIDE + kk + bcol) * 2);
                ldmx2(bh[ni], base + 2 * TILE_B + bd);
                ldmx2(bl[ni], base + 3 * TILE_B + bd);
            }
#pragma unroll
            for (int mi = 0; mi < 4; mi++)
#pragma unroll
                for (int ni = 0; ni < 4; ni++) {
                    mma_bf16(acc[mi][ni], ah[mi], bh[ni]);
                    mma_bf16(acc[mi][ni], ah[mi], bl[ni]);
                    mma_bf16(acc[mi][ni], al[mi], bh[ni]);
                }
        }
        if (t + 1 < T) {
            STORES((t + 1) & 1);
            __syncthreads();
        }
    }
#undef LOADG
#undef STORES

    // ---------------- epilogue ----------------
    if (TRANS) {
        __syncthreads();                 // smem tiles no longer needed
        float* st = (float*)smem;        // [128 n][132]
#pragma unroll
        for (int mi = 0; mi < 4; mi++) {
            int rowl = warp_m * 64 + mi * 16 + (lane >> 2);
#pragma unroll
            for (int ni = 0; ni < 4; ni++) {
                int coll = warp_n * 32 + ni * 8 + (lane & 3) * 2;
                float b0 = bias[n0 + coll], b1 = bias[n0 + coll + 1];
                st[coll * 132 + rowl]           = acc[mi][ni][0] + b0;
                st[(coll + 1) * 132 + rowl]     = acc[mi][ni][1] + b1;
                st[coll * 132 + rowl + 8]       = acc[mi][ni][2] + b0;
                st[(coll + 1) * 132 + rowl + 8] = acc[mi][ni][3] + b1;
            }
        }
        __syncthreads();
        int bz  = m0 >> 11;
        int m0s = m0 & (SEQ - 1);
        for (int w = tid; w < 128 * 64; w += 256) {
            int d = w >> 6, mp = w & 63;
            float v0 = st[d * 132 + mp * 2];
            float v1 = st[d * 132 + mp * 2 + 1];
            float h0 = __bfloat162float(__float2bfloat16(v0));
            float h1 = __bfloat162float(__float2bfloat16(v1));
            size_t idx = (((size_t)(bz * DIM + n0 + d) * SEQ + m0s) >> 1) + mp;
            ((uint32_t*)g_vth)[idx] = pack2bf(h0, h1);
            ((uint32_t*)g_vtl)[idx] = pack2bf(v0 - h0, v1 - h1);
        }
    } else {
        float* C = Cout + (size_t)z * sC;
#pragma unroll
        for (int mi = 0; mi < 4; mi++) {
            int row = m0 + warp_m * 64 + mi * 16 + (lane >> 2);
#pragma unroll
            for (int ni = 0; ni < 4; ni++) {
                int col = n0 + warp_n * 32 + ni * 8 + (lane & 3) * 2;
                *(float2*)&C[(size_t)row * Ndim + col] =
                    make_float2(acc[mi][ni][0], acc[mi][ni][1]);
                *(float2*)&C[(size_t)(row + 8) * Ndim + col] =
                    make_float2(acc[mi][ni][2], acc[mi][ni][3]);
            }
        }
    }
}

// ======================= launch =============================================
extern "C" void kernel_launch(void* const* d_in, const int* in_sizes, int n_in,
                              void* d_out, int out_size)
{
    const float* x     = (const float*)d_in[0];
    const float* basis = (const float*)d_in[1];
    const float* Wq    = (const float*)d_in[2];
    const float* bq    = (const float*)d_in[3];
    const float* Wk    = (const float*)d_in[4];
    const float* bk    = (const float*)d_in[5];
    const float* Wv    = (const float*)d_in[6];
    const float* bv    = (const float*)d_in[7];
    float* out = (float*)d_out;

    __nv_bfloat16 *pxh, *pxl, *pwh, *pwl, *pph, *ppl, *pvth, *pvtl;
    cudaGetSymbolAddress((void**)&pxh, g_xh);
    cudaGetSymbolAddress((void**)&pxl, g_xl);
    cudaGetSymbolAddress((void**)&pwh, g_wh);
    cudaGetSymbolAddress((void**)&pwl, g_wl);
    cudaGetSymbolAddress((void**)&pph, g_ph);
    cudaGetSymbolAddress((void**)&ppl, g_pl);
    cudaGetSymbolAddress((void**)&pvth, g_vth);
    cudaGetSymbolAddress((void**)&pvtl, g_vtl);

    cudaFuncSetAttribute(mma_gemm<true>,  cudaFuncAttributeMaxDynamicSharedMemorySize, MM_SMEM);
    cudaFuncSetAttribute(mma_gemm<false>, cudaFuncAttributeMaxDynamicSharedMemorySize, MM_SMEM);

    // splits
    split_kernel<<<MTOK * DIM / 4 / 256, 256>>>(x, pxh, pxl);
    split_kernel<<<DIM * DIM / 4 / 256, 256>>>(Wv, pwh, pwl);

    // fold (bf16-split C + biases)
    fold_kernel<<<dim3(4, 32), 256>>>(basis, Wq, bq, Wk, bk);

    // kan via mma.sync (needs split x + folded C)
    kan_mma_kernel<<<MTOK / 128, 256>>>();

    // K3: v = x @ Wv^T + bv  -> vT (bf16 split), mma.sync
    mma_gemm<true><<<dim3(DIM / 128, MTOK / 128, 1), 256, MM_SMEM>>>(
        pxh, pxl, pwh, pwl, bv, nullptr, DIM, DIM, 0L, 0L, 0L);

    // K4: scores + softmax (-> bf16 split P)
    score_kernel<<<dim3(SEQ / 128, SEQ / 128, NB), 256>>>();
    softmax_kernel<<<MTOK, 256>>>();

    // K5: out = P @ v  (= P @ (vT)^T), mma.sync
    mma_gemm<false><<<dim3(DIM / 128, SEQ / 128, NB), 256, MM_SMEM>>>(
        pph, ppl, pvth, pvtl, nullptr, out, SEQ, DIM,
        (long)SEQ * SEQ, (long)DIM * SEQ, (long)SEQ * DIM);
}